// round 1
// baseline (speedup 1.0000x reference)
#include <cuda_runtime.h>
#include <math.h>

#define BB   4
#define SEQ  2048
#define DM   1024
#define NH   16
#define HDIM 64
#define BH   (BB * NH)

// Scratch: q,k,v in [B,H,N,HD] layout. 3 x 32 MiB device globals (allowed).
__device__ float g_q[BB * NH * SEQ * HDIM];
__device__ float g_k[BB * NH * SEQ * HDIM];
__device__ float g_v[BB * NH * SEQ * HDIM];

// ---------------------------------------------------------------------------
// Kernel 1: fused QKV projection.  Y = X @ W + b, written into [B,H,N,HD].
// Tile 128x128xK16, 256 threads, 8x8 micro-tile per thread.
// grid.z selects (Wq,bq)->g_q, (Wk,bk)->g_k, (Wv,bv)->g_v.
// ---------------------------------------------------------------------------
#define GTM 128
#define GTN 128
#define GTK 16

__global__ __launch_bounds__(256, 2)
void qkv_gemm_kernel(const float* __restrict__ X,
                     const float* __restrict__ Wq, const float* __restrict__ bq,
                     const float* __restrict__ Wk, const float* __restrict__ bk,
                     const float* __restrict__ Wv, const float* __restrict__ bv)
{
    __shared__ float Ast[GTK][GTM];   // A transposed: [k][m]
    __shared__ float Bs [GTK][GTN];   // B: [k][n]

    const int z = blockIdx.z;
    const float* W    = (z == 0) ? Wq : (z == 1) ? Wk : Wv;
    const float* bias = (z == 0) ? bq : (z == 1) ? bk : bv;
    float*       Out  = (z == 0) ? g_q : (z == 1) ? g_k : g_v;

    const int tid = threadIdx.x;
    const int m0  = blockIdx.y * GTM;
    const int n0  = blockIdx.x * GTN;
    const int tx  = tid & 15;
    const int ty  = tid >> 4;

    float acc[8][8];
    #pragma unroll
    for (int i = 0; i < 8; i++)
        #pragma unroll
        for (int j = 0; j < 8; j++) acc[i][j] = 0.0f;

    for (int k0 = 0; k0 < DM; k0 += GTK) {
        // Load A tile (128x16) transposed into Ast[k][m].
        #pragma unroll
        for (int it = 0; it < 2; it++) {
            int idx = tid + it * 256;          // 0..511 float4 slots
            int row = idx >> 2;                // 0..127
            int kq  = (idx & 3) << 2;          // 0,4,8,12
            float4 v = *(const float4*)(X + (m0 + row) * DM + k0 + kq);
            Ast[kq + 0][row] = v.x;
            Ast[kq + 1][row] = v.y;
            Ast[kq + 2][row] = v.z;
            Ast[kq + 3][row] = v.w;
        }
        // Load B tile (16x128) into Bs[k][n].
        #pragma unroll
        for (int it = 0; it < 2; it++) {
            int idx = tid + it * 256;
            int row = idx >> 5;                // 0..15
            int cq  = (idx & 31) << 2;         // 0..124
            *(float4*)&Bs[row][cq] =
                *(const float4*)(W + (k0 + row) * DM + n0 + cq);
        }
        __syncthreads();

        #pragma unroll 4
        for (int k = 0; k < GTK; k++) {
            float a[8], b[8];
            *(float4*)&a[0] = *(float4*)&Ast[k][ty * 8];
            *(float4*)&a[4] = *(float4*)&Ast[k][ty * 8 + 4];
            *(float4*)&b[0] = *(float4*)&Bs [k][tx * 8];
            *(float4*)&b[4] = *(float4*)&Bs [k][tx * 8 + 4];
            #pragma unroll
            for (int i = 0; i < 8; i++)
                #pragma unroll
                for (int j = 0; j < 8; j++)
                    acc[i][j] += a[i] * b[j];
        }
        __syncthreads();
    }

    // Epilogue: add bias, write to [B,H,N,HD].
    #pragma unroll
    for (int i = 0; i < 8; i++) {
        int m    = m0 + ty * 8 + i;
        int bidx = m / SEQ;
        int n    = m % SEQ;
        #pragma unroll
        for (int jj = 0; jj < 2; jj++) {
            int e  = n0 + tx * 8 + jj * 4;
            int h  = e >> 6;
            int hd = e & 63;
            float4 v;
            v.x = acc[i][jj * 4 + 0] + bias[e + 0];
            v.y = acc[i][jj * 4 + 1] + bias[e + 1];
            v.z = acc[i][jj * 4 + 2] + bias[e + 2];
            v.w = acc[i][jj * 4 + 3] + bias[e + 3];
            *(float4*)(Out + ((bidx * NH + h) * SEQ + n) * HDIM + hd) = v;
        }
    }
}

// ---------------------------------------------------------------------------
// Kernel 2: causal flash attention, fp32, online softmax.
// Per block: one (b,h) and a 64-query tile; loop over 64-key tiles.
// 256 threads, 4x4 micro-tiles; S and PV as small smem GEMMs.
// ---------------------------------------------------------------------------
#define AT  64
#define AST 68   // smem row stride (floats): mult of 4 (f4-aligned), banks spread

__global__ __launch_bounds__(256)
void flash_kernel(float* __restrict__ out)
{
    extern __shared__ float sm[];
    float* Qt  = sm;                 // [64][AST]  Q^T, pre-scaled by 1/8
    float* Kt  = sm + 1 * AT * AST;  // [64][AST]  K^T
    float* Vs  = sm + 2 * AT * AST;  // [64][AST]  V (row = key, col = d)
    float* Pst = sm + 3 * AT * AST;  // [64][AST]  P^T

    const int tid = threadIdx.x;
    const int tx  = tid & 15;        // S col group / O d-col group
    const int ty  = tid >> 4;        // S/O row group
    const int qt  = blockIdx.x;
    const int bh  = blockIdx.y;
    const int q0  = qt * AT;

    const float* Qg = g_q + (size_t)bh * SEQ * HDIM;
    const float* Kg = g_k + (size_t)bh * SEQ * HDIM;
    const float* Vg = g_v + (size_t)bh * SEQ * HDIM;

    const float inv_scale = 0.125f;  // 1/sqrt(HD=64)

    // Load Q tile transposed (scaled).
    {
        int r  = tid >> 2;           // 0..63
        int kb = (tid & 3) << 4;     // 0,16,32,48
        #pragma unroll
        for (int it = 0; it < 4; it++) {
            float4 v = *(const float4*)(Qg + (q0 + r) * HDIM + kb + it * 4);
            int kk = kb + it * 4;
            Qt[(kk + 0) * AST + r] = v.x * inv_scale;
            Qt[(kk + 1) * AST + r] = v.y * inv_scale;
            Qt[(kk + 2) * AST + r] = v.z * inv_scale;
            Qt[(kk + 3) * AST + r] = v.w * inv_scale;
        }
    }

    float m_i[4], l_i[4], acc[4][4];
    #pragma unroll
    for (int i = 0; i < 4; i++) {
        m_i[i] = -INFINITY;
        l_i[i] = 0.0f;
        #pragma unroll
        for (int j = 0; j < 4; j++) acc[i][j] = 0.0f;
    }

    for (int jt = 0; jt <= qt; jt++) {
        const int k0 = jt * AT;
        __syncthreads();  // prev PV done (and Qt ready on first iter) before reuse

        // Load K transposed and V direct.
        {
            int c  = tid >> 2;
            int kb = (tid & 3) << 4;
            #pragma unroll
            for (int it = 0; it < 4; it++) {
                int kk = kb + it * 4;
                float4 v = *(const float4*)(Kg + (k0 + c) * HDIM + kk);
                Kt[(kk + 0) * AST + c] = v.x;
                Kt[(kk + 1) * AST + c] = v.y;
                Kt[(kk + 2) * AST + c] = v.z;
                Kt[(kk + 3) * AST + c] = v.w;
                *(float4*)&Vs[c * AST + kk] =
                    *(const float4*)(Vg + (k0 + c) * HDIM + kk);
            }
        }
        __syncthreads();

        // S = (Q/8) K^T   (rows ty*4+i, cols tx*4+j)
        float s[4][4];
        #pragma unroll
        for (int i = 0; i < 4; i++)
            #pragma unroll
            for (int j = 0; j < 4; j++) s[i][j] = 0.0f;

        #pragma unroll 8
        for (int kk = 0; kk < AT; kk++) {
            float a[4], b[4];
            *(float4*)a = *(float4*)&Qt[kk * AST + ty * 4];
            *(float4*)b = *(float4*)&Kt[kk * AST + tx * 4];
            #pragma unroll
            for (int i = 0; i < 4; i++)
                #pragma unroll
                for (int j = 0; j < 4; j++)
                    s[i][j] += a[i] * b[j];
        }

        // Causal mask on the diagonal tile.
        if (jt == qt) {
            #pragma unroll
            for (int i = 0; i < 4; i++)
                #pragma unroll
                for (int j = 0; j < 4; j++)
                    if (tx * 4 + j > ty * 4 + i) s[i][j] = -1e30f;
        }

        // Online softmax update (row reductions across the 16 tx lanes).
        float alpha[4];
        #pragma unroll
        for (int i = 0; i < 4; i++) {
            float mx = s[i][0];
            mx = fmaxf(mx, s[i][1]);
            mx = fmaxf(mx, s[i][2]);
            mx = fmaxf(mx, s[i][3]);
            #pragma unroll
            for (int o = 8; o; o >>= 1)
                mx = fmaxf(mx, __shfl_xor_sync(0xffffffffu, mx, o));
            float mnew = fmaxf(m_i[i], mx);
            float a_   = __expf(m_i[i] - mnew);
            float ps = 0.0f;
            #pragma unroll
            for (int j = 0; j < 4; j++) {
                float p = __expf(s[i][j] - mnew);
                s[i][j] = p;
                ps += p;
            }
            #pragma unroll
            for (int o = 8; o; o >>= 1)
                ps += __shfl_xor_sync(0xffffffffu, ps, o);
            l_i[i]   = l_i[i] * a_ + ps;
            m_i[i]   = mnew;
            alpha[i] = a_;
        }

        #pragma unroll
        for (int i = 0; i < 4; i++)
            #pragma unroll
            for (int j = 0; j < 4; j++) acc[i][j] *= alpha[i];

        // Write P transposed: Pst[c][r].
        #pragma unroll
        for (int i = 0; i < 4; i++)
            #pragma unroll
            for (int j = 0; j < 4; j++)
                Pst[(tx * 4 + j) * AST + ty * 4 + i] = s[i][j];
        __syncthreads();

        // O += P V   (rows ty*4+i, d-cols tx*4+j)
        #pragma unroll 8
        for (int c = 0; c < AT; c++) {
            float a[4], b[4];
            *(float4*)a = *(float4*)&Pst[c * AST + ty * 4];
            *(float4*)b = *(float4*)&Vs [c * AST + tx * 4];
            #pragma unroll
            for (int i = 0; i < 4; i++)
                #pragma unroll
                for (int j = 0; j < 4; j++)
                    acc[i][j] += a[i] * b[j];
        }
    }

    // Epilogue: normalize and write [B,N,D] output.
    const int b = bh / NH;
    const int h = bh % NH;
    #pragma unroll
    for (int i = 0; i < 4; i++) {
        int n = q0 + ty * 4 + i;
        float invl = 1.0f / l_i[i];
        float4 v;
        v.x = acc[i][0] * invl;
        v.y = acc[i][1] * invl;
        v.z = acc[i][2] * invl;
        v.w = acc[i][3] * invl;
        *(float4*)(out + ((size_t)(b * SEQ + n)) * DM + h * HDIM + tx * 4) = v;
    }
}

// ---------------------------------------------------------------------------
// Launch
// ---------------------------------------------------------------------------
extern "C" void kernel_launch(void* const* d_in, const int* in_sizes, int n_in,
                              void* d_out, int out_size)
{
    const float* x = (const float*)d_in[0];

    // The mask input (N*N elements) is static causal; detect & skip it so we
    // are robust to whether the harness passes it.
    int base = 1;
    if (n_in >= 8 && in_sizes[1] == SEQ * SEQ) base = 2;

    const float* Wq = (const float*)d_in[base + 0];
    const float* bq = (const float*)d_in[base + 1];
    const float* Wk = (const float*)d_in[base + 2];
    const float* bk = (const float*)d_in[base + 3];
    const float* Wv = (const float*)d_in[base + 4];
    const float* bv = (const float*)d_in[base + 5];
    float* out = (float*)d_out;

    const int smem_flash = 4 * AT * AST * (int)sizeof(float);  // 69,632 B
    cudaFuncSetAttribute(flash_kernel,
                         cudaFuncAttributeMaxDynamicSharedMemorySize,
                         smem_flash);

    dim3 g1(DM / GTN, (BB * SEQ) / GTM, 3);   // (8, 64, 3)
    qkv_gemm_kernel<<<g1, 256>>>(x, Wq, bq, Wk, bk, Wv, bv);

    dim3 g2(SEQ / AT, BH);                    // (32, 64)
    flash_kernel<<<g2, 256, smem_flash>>>(out);
}

// round 2
// speedup vs baseline: 3.4076x; 3.4076x over previous
#include <cuda_runtime.h>
#include <math.h>
#include <stdint.h>

#define BB   4
#define SEQ  2048
#define DM   1024
#define NH   16
#define HDIM 64
#define BH   (BB * NH)

// Scratch: q,k,v in [B,H,N,HD] layout (fp32). 3 x 32 MiB device globals.
__device__ float g_q[BB * NH * SEQ * HDIM];
__device__ float g_k[BB * NH * SEQ * HDIM];
__device__ float g_v[BB * NH * SEQ * HDIM];

// ---------------------------------------------------------------------------
// tf32 helpers
// ---------------------------------------------------------------------------
__device__ __forceinline__ uint32_t f2tf(float x) {
    uint32_t u;
    asm("cvt.rna.tf32.f32 %0, %1;" : "=r"(u) : "f"(x));
    return u;
}

// D += A(16x8) * B(8x8), tf32 in, fp32 accum.
__device__ __forceinline__ void mma8(float c[4], const uint32_t a[4],
                                     const uint32_t b[2]) {
    asm volatile(
        "mma.sync.aligned.m16n8k8.row.col.f32.tf32.tf32.f32 "
        "{%0,%1,%2,%3}, {%4,%5,%6,%7}, {%8,%9}, {%0,%1,%2,%3};\n"
        : "+f"(c[0]), "+f"(c[1]), "+f"(c[2]), "+f"(c[3])
        : "r"(a[0]), "r"(a[1]), "r"(a[2]), "r"(a[3]), "r"(b[0]), "r"(b[1]));
}

// ---------------------------------------------------------------------------
// Kernel 1: fused QKV projection via tf32 HMMA.
// Block tile 128x128, k-step 32. 8 warps in 4(m) x 2(n); each warp 32x64.
// grid.z selects (Wq,bq)->g_q, (Wk,bk)->g_k, (Wv,bv)->g_v.
// ---------------------------------------------------------------------------
#define SA 36    // A smem stride (floats): banks (4g+t) -> conflict-free frags
#define SB 136   // B smem stride: banks (8t+g) -> conflict-free frags

__global__ __launch_bounds__(256, 2)
void qkv_gemm_tf32(const float* __restrict__ X,
                   const float* __restrict__ Wq, const float* __restrict__ bq,
                   const float* __restrict__ Wk, const float* __restrict__ bk,
                   const float* __restrict__ Wv, const float* __restrict__ bv)
{
    __shared__ uint32_t As[128 * SA];   // [m][k] tf32
    __shared__ uint32_t Bs[32 * SB];    // [k][n] tf32

    const int z = blockIdx.z;
    const float* W    = (z == 0) ? Wq : (z == 1) ? Wk : Wv;
    const float* bias = (z == 0) ? bq : (z == 1) ? bk : bv;
    float*       Out  = (z == 0) ? g_q : (z == 1) ? g_k : g_v;

    const int tid  = threadIdx.x;
    const int lane = tid & 31;
    const int warp = tid >> 5;
    const int mw   = warp >> 1;        // 0..3
    const int nw   = warp & 1;         // 0..1
    const int g    = lane >> 2;        // 0..7
    const int t    = lane & 3;         // 0..3
    const int m0   = blockIdx.y * 128;
    const int n0   = blockIdx.x * 128;

    float c[2][8][4];
    #pragma unroll
    for (int mt = 0; mt < 2; mt++)
        #pragma unroll
        for (int nt = 0; nt < 8; nt++)
            #pragma unroll
            for (int r = 0; r < 4; r++) c[mt][nt][r] = 0.0f;

    for (int k0 = 0; k0 < DM; k0 += 32) {
        // A tile: 128x32 floats -> tf32 smem
        #pragma unroll
        for (int it = 0; it < 4; it++) {
            int idx = tid + it * 256;            // 0..1023 float4 slots
            int row = idx >> 3;                  // 0..127
            int kq  = (idx & 7) << 2;            // 0..28
            float4 v = *(const float4*)(X + (size_t)(m0 + row) * DM + k0 + kq);
            uint4 u;
            u.x = f2tf(v.x); u.y = f2tf(v.y); u.z = f2tf(v.z); u.w = f2tf(v.w);
            *(uint4*)&As[row * SA + kq] = u;
        }
        // B tile: 32x128
        #pragma unroll
        for (int it = 0; it < 4; it++) {
            int idx = tid + it * 256;
            int row = idx >> 5;                  // 0..31
            int cq  = (idx & 31) << 2;           // 0..124
            float4 v = *(const float4*)(W + (size_t)(k0 + row) * DM + n0 + cq);
            uint4 u;
            u.x = f2tf(v.x); u.y = f2tf(v.y); u.z = f2tf(v.z); u.w = f2tf(v.w);
            *(uint4*)&Bs[row * SB + cq] = u;
        }
        __syncthreads();

        #pragma unroll
        for (int kt = 0; kt < 4; kt++) {
            const int kk = kt * 8;
            uint32_t a[2][4];
            #pragma unroll
            for (int mt = 0; mt < 2; mt++) {
                int base = (mw * 32 + mt * 16 + g) * SA + kk + t;
                a[mt][0] = As[base];
                a[mt][1] = As[base + 8 * SA];
                a[mt][2] = As[base + 4];
                a[mt][3] = As[base + 8 * SA + 4];
            }
            uint32_t b[8][2];
            #pragma unroll
            for (int nt = 0; nt < 8; nt++) {
                int base = (kk + t) * SB + nw * 64 + nt * 8 + g;
                b[nt][0] = Bs[base];
                b[nt][1] = Bs[base + 4 * SB];
            }
            #pragma unroll
            for (int mt = 0; mt < 2; mt++)
                #pragma unroll
                for (int nt = 0; nt < 8; nt++)
                    mma8(c[mt][nt], a[mt], b[nt]);
        }
        __syncthreads();
    }

    // Epilogue: bias add, scatter to [B,H,N,HD].
    #pragma unroll
    for (int mt = 0; mt < 2; mt++) {
        int m    = m0 + mw * 32 + mt * 16 + g;   // m and m+8 stay in same batch
        int bidx = m >> 11;                      // / SEQ
        int n    = m & (SEQ - 1);
        #pragma unroll
        for (int nt = 0; nt < 8; nt++) {
            int col = n0 + nw * 64 + nt * 8 + 2 * t;
            int h   = col >> 6;
            int hd  = col & 63;
            float bx = bias[col], by = bias[col + 1];
            float* base = Out + ((size_t)((bidx * NH + h) * SEQ + n)) * HDIM + hd;
            float2 v0 = { c[mt][nt][0] + bx, c[mt][nt][1] + by };
            *(float2*)base = v0;
            float2 v1 = { c[mt][nt][2] + bx, c[mt][nt][3] + by };
            *(float2*)(base + 8 * HDIM) = v1;
        }
    }
}

// ---------------------------------------------------------------------------
// Kernel 2: causal flash attention via tf32 HMMA.
// Block: one (b,h), 128-query tile; loop over 64-key tiles.
// 8 warps; warp w owns S/O rows [16w, 16w+16). Q frags preloaded to regs.
// P round-trips through warp-private smem (reuses Q smem region).
// ---------------------------------------------------------------------------
#define SQP 68   // Q/K/P stride: frag banks (4g+t) conflict-free
#define SVP 72   // V stride:     frag banks (8t+g) conflict-free

__global__ __launch_bounds__(256, 2)
void flash_tf32(float* __restrict__ out)
{
    extern __shared__ uint32_t sm[];
    uint32_t* sQ = sm;                    // [128][SQP]; reused as Pst
    uint32_t* sK = sm + 128 * SQP;        // [64][SQP]
    uint32_t* sV = sK + 64 * SQP;         // [64][SVP]

    const int tid  = threadIdx.x;
    const int lane = tid & 31;
    const int warp = tid >> 5;
    const int g    = lane >> 2;
    const int t    = lane & 3;
    const int qt   = blockIdx.x;
    const int bh   = blockIdx.y;
    const int q0   = qt * 128;

    const float* Qg = g_q + (size_t)bh * SEQ * HDIM;
    const float* Kg = g_k + (size_t)bh * SEQ * HDIM;
    const float* Vg = g_v + (size_t)bh * SEQ * HDIM;

    // Load Q tile, scaled by 1/sqrt(64), as tf32.
    #pragma unroll
    for (int it = 0; it < 8; it++) {
        int idx = tid + it * 256;            // 0..2047 float4 slots
        int row = idx >> 4;                  // 0..127
        int cq  = (idx & 15) << 2;           // 0..60
        float4 v = *(const float4*)(Qg + (size_t)(q0 + row) * HDIM + cq);
        uint4 u;
        u.x = f2tf(v.x * 0.125f); u.y = f2tf(v.y * 0.125f);
        u.z = f2tf(v.z * 0.125f); u.w = f2tf(v.w * 0.125f);
        *(uint4*)&sQ[row * SQP + cq] = u;
    }
    __syncthreads();

    // Preload Q fragments (warp-private rows).
    uint32_t qa[8][4];
    #pragma unroll
    for (int kt = 0; kt < 8; kt++) {
        int base = (warp * 16 + g) * SQP + kt * 8 + t;
        qa[kt][0] = sQ[base];
        qa[kt][1] = sQ[base + 8 * SQP];
        qa[kt][2] = sQ[base + 4];
        qa[kt][3] = sQ[base + 8 * SQP + 4];
    }
    uint32_t* Pst = sQ + warp * 16 * SQP;    // warp-private P tile [16][SQP]

    float o[8][4];
    #pragma unroll
    for (int nt = 0; nt < 8; nt++)
        #pragma unroll
        for (int r = 0; r < 4; r++) o[nt][r] = 0.0f;
    float m0r = -INFINITY, m1r = -INFINITY, l0 = 0.0f, l1 = 0.0f;

    const int nkt = 2 * qt + 2;
    for (int jt = 0; jt < nkt; jt++) {
        const int k0 = jt * 64;
        __syncthreads();   // all warps done with prior sK/sV (and P reads)

        // Load K and V tiles as tf32.
        #pragma unroll
        for (int it = 0; it < 4; it++) {
            int idx = tid + it * 256;        // 0..1023 float4 slots
            int row = idx >> 4;              // 0..63
            int cq  = (idx & 15) << 2;       // 0..60
            float4 kv = *(const float4*)(Kg + (size_t)(k0 + row) * HDIM + cq);
            uint4 uk;
            uk.x = f2tf(kv.x); uk.y = f2tf(kv.y);
            uk.z = f2tf(kv.z); uk.w = f2tf(kv.w);
            *(uint4*)&sK[row * SQP + cq] = uk;
            float4 vv = *(const float4*)(Vg + (size_t)(k0 + row) * HDIM + cq);
            uint4 uv;
            uv.x = f2tf(vv.x); uv.y = f2tf(vv.y);
            uv.z = f2tf(vv.z); uv.w = f2tf(vv.w);
            *(uint4*)&sV[row * SVP + cq] = uv;
        }
        __syncthreads();

        // S = (Q/8) K^T  : warp rows 16, cols 64.
        float s[8][4];
        #pragma unroll
        for (int nt = 0; nt < 8; nt++)
            #pragma unroll
            for (int r = 0; r < 4; r++) s[nt][r] = 0.0f;

        #pragma unroll
        for (int kt = 0; kt < 8; kt++) {
            uint32_t b2[8][2];
            #pragma unroll
            for (int nt = 0; nt < 8; nt++) {
                int base = (nt * 8 + g) * SQP + kt * 8 + t;
                b2[nt][0] = sK[base];
                b2[nt][1] = sK[base + 4];
            }
            #pragma unroll
            for (int nt = 0; nt < 8; nt++) mma8(s[nt], qa[kt], b2[nt]);
        }

        // Causal mask (only last two key tiles can intersect the diagonal).
        if (jt >= 2 * qt) {
            int r0 = q0 + warp * 16 + g;
            int r1 = r0 + 8;
            #pragma unroll
            for (int nt = 0; nt < 8; nt++) {
                int key = k0 + nt * 8 + 2 * t;
                if (key     > r0) s[nt][0] = -1e30f;
                if (key + 1 > r0) s[nt][1] = -1e30f;
                if (key     > r1) s[nt][2] = -1e30f;
                if (key + 1 > r1) s[nt][3] = -1e30f;
            }
        }

        // Online softmax: thread owns 16 cols of rows r0 (regs 0,1) and r1 (2,3).
        float mx0 = -INFINITY, mx1 = -INFINITY;
        #pragma unroll
        for (int nt = 0; nt < 8; nt++) {
            mx0 = fmaxf(mx0, fmaxf(s[nt][0], s[nt][1]));
            mx1 = fmaxf(mx1, fmaxf(s[nt][2], s[nt][3]));
        }
        mx0 = fmaxf(mx0, __shfl_xor_sync(0xffffffffu, mx0, 1));
        mx0 = fmaxf(mx0, __shfl_xor_sync(0xffffffffu, mx0, 2));
        mx1 = fmaxf(mx1, __shfl_xor_sync(0xffffffffu, mx1, 1));
        mx1 = fmaxf(mx1, __shfl_xor_sync(0xffffffffu, mx1, 2));

        float mn0 = fmaxf(m0r, mx0), mn1 = fmaxf(m1r, mx1);
        float a0 = __expf(m0r - mn0), a1 = __expf(m1r - mn1);
        float ps0 = 0.0f, ps1 = 0.0f;
        #pragma unroll
        for (int nt = 0; nt < 8; nt++) {
            s[nt][0] = __expf(s[nt][0] - mn0); ps0 += s[nt][0];
            s[nt][1] = __expf(s[nt][1] - mn0); ps0 += s[nt][1];
            s[nt][2] = __expf(s[nt][2] - mn1); ps1 += s[nt][2];
            s[nt][3] = __expf(s[nt][3] - mn1); ps1 += s[nt][3];
        }
        ps0 += __shfl_xor_sync(0xffffffffu, ps0, 1);
        ps0 += __shfl_xor_sync(0xffffffffu, ps0, 2);
        ps1 += __shfl_xor_sync(0xffffffffu, ps1, 1);
        ps1 += __shfl_xor_sync(0xffffffffu, ps1, 2);
        l0 = l0 * a0 + ps0; l1 = l1 * a1 + ps1;
        m0r = mn0; m1r = mn1;

        #pragma unroll
        for (int nt = 0; nt < 8; nt++) {
            o[nt][0] *= a0; o[nt][1] *= a0;
            o[nt][2] *= a1; o[nt][3] *= a1;
        }

        // P -> warp-private smem as tf32.
        #pragma unroll
        for (int nt = 0; nt < 8; nt++) {
            uint2 u0; u0.x = f2tf(s[nt][0]); u0.y = f2tf(s[nt][1]);
            *(uint2*)&Pst[g * SQP + nt * 8 + 2 * t] = u0;
            uint2 u1; u1.x = f2tf(s[nt][2]); u1.y = f2tf(s[nt][3]);
            *(uint2*)&Pst[(g + 8) * SQP + nt * 8 + 2 * t] = u1;
        }
        __syncwarp();

        // O += P V
        #pragma unroll
        for (int kt = 0; kt < 8; kt++) {
            uint32_t pa[4];
            int base = g * SQP + kt * 8 + t;
            pa[0] = Pst[base];
            pa[1] = Pst[base + 8 * SQP];
            pa[2] = Pst[base + 4];
            pa[3] = Pst[base + 8 * SQP + 4];
            #pragma unroll
            for (int nt = 0; nt < 8; nt++) {
                uint32_t vb[2];
                int vbase = (kt * 8 + t) * SVP + nt * 8 + g;
                vb[0] = sV[vbase];
                vb[1] = sV[vbase + 4 * SVP];
                mma8(o[nt], pa, vb);
            }
        }
    }

    // Epilogue: normalize, write [B,N,D].
    const int b  = bh >> 4;
    const int h  = bh & 15;
    const int r0 = q0 + warp * 16 + g;
    const float i0 = 1.0f / l0, i1 = 1.0f / l1;
    #pragma unroll
    for (int nt = 0; nt < 8; nt++) {
        int col = h * HDIM + nt * 8 + 2 * t;
        float2 v0 = { o[nt][0] * i0, o[nt][1] * i0 };
        *(float2*)(out + ((size_t)(b * SEQ + r0)) * DM + col) = v0;
        float2 v1 = { o[nt][2] * i1, o[nt][3] * i1 };
        *(float2*)(out + ((size_t)(b * SEQ + r0 + 8)) * DM + col) = v1;
    }
}

// ---------------------------------------------------------------------------
// Launch
// ---------------------------------------------------------------------------
extern "C" void kernel_launch(void* const* d_in, const int* in_sizes, int n_in,
                              void* d_out, int out_size)
{
    const float* x = (const float*)d_in[0];

    // Static causal mask input (N*N elements) detected & skipped.
    int base = 1;
    if (n_in >= 8 && in_sizes[1] == SEQ * SEQ) base = 2;

    const float* Wq = (const float*)d_in[base + 0];
    const float* bq = (const float*)d_in[base + 1];
    const float* Wk = (const float*)d_in[base + 2];
    const float* bk = (const float*)d_in[base + 3];
    const float* Wv = (const float*)d_in[base + 4];
    const float* bv = (const float*)d_in[base + 5];
    float* out = (float*)d_out;

    const int smem_flash = (128 * SQP + 64 * SQP + 64 * SVP) * (int)sizeof(uint32_t);
    cudaFuncSetAttribute(flash_tf32,
                         cudaFuncAttributeMaxDynamicSharedMemorySize,
                         smem_flash);

    dim3 g1(DM / 128, (BB * SEQ) / 128, 3);   // (8, 64, 3)
    qkv_gemm_tf32<<<g1, 256>>>(x, Wq, bq, Wk, bk, Wv, bv);

    dim3 g2(SEQ / 128, BH);                   // (16, 64)
    flash_tf32<<<g2, 256, smem_flash>>>(out);
}

// round 4
// speedup vs baseline: 6.7630x; 1.9847x over previous
#include <cuda_runtime.h>
#include <cuda_fp16.h>
#include <math.h>
#include <stdint.h>

#define BB   4
#define SEQ  2048
#define DM   1024
#define NH   16
#define HDIM 64
#define BH   (BB * NH)

// Scratch device globals (allowed).
__device__ __half g_qh[BB * NH * SEQ * HDIM];   // Q (pre-scaled by 1/8)
__device__ __half g_kh[BB * NH * SEQ * HDIM];
__device__ __half g_vh[BB * NH * SEQ * HDIM];
__device__ __half g_xh[BB * SEQ * DM];          // X as fp16
__device__ __half g_wh[3 * DM * DM];            // W^T [z][n][k] as fp16

// ---------------------------------------------------------------------------
// Helpers
// ---------------------------------------------------------------------------
__device__ __forceinline__ uint32_t smem_u32(const void* p) {
    uint32_t a;
    asm("{ .reg .u64 t; cvta.to.shared.u64 t, %1; cvt.u32.u64 %0, t; }"
        : "=r"(a) : "l"(p));
    return a;
}
__device__ __forceinline__ uint32_t packh2(float x, float y) {
    __half2 h = __floats2half2_rn(x, y);          // low = x, high = y
    return *(uint32_t*)&h;
}
// D += A(16x16) * B(16x8), fp16 in, fp32 accum.
__device__ __forceinline__ void mma16(float c[4], const uint32_t a[4],
                                      uint32_t b0, uint32_t b1) {
    asm volatile(
        "mma.sync.aligned.m16n8k16.row.col.f32.f16.f16.f32 "
        "{%0,%1,%2,%3}, {%4,%5,%6,%7}, {%8,%9}, {%0,%1,%2,%3};\n"
        : "+f"(c[0]), "+f"(c[1]), "+f"(c[2]), "+f"(c[3])
        : "r"(a[0]), "r"(a[1]), "r"(a[2]), "r"(a[3]), "r"(b0), "r"(b1));
}
__device__ __forceinline__ void ldsm4t(uint32_t r[4], uint32_t addr) {
    asm volatile(
        "ldmatrix.sync.aligned.m8n8.x4.trans.shared.b16 {%0,%1,%2,%3}, [%4];"
        : "=r"(r[0]), "=r"(r[1]), "=r"(r[2]), "=r"(r[3]) : "r"(addr));
}
__device__ __forceinline__ void cp16(uint32_t dst, const void* src) {
    asm volatile("cp.async.cg.shared.global [%0], [%1], 16;" :: "r"(dst), "l"(src));
}

// ---------------------------------------------------------------------------
// Prep kernels: X -> fp16; W -> W^T fp16.
// ---------------------------------------------------------------------------
__global__ void prep_x(const float* __restrict__ X) {
    size_t i = ((size_t)blockIdx.x * blockDim.x + threadIdx.x) * 4;
    float4 v = *(const float4*)(X + i);
    uint2 u;
    u.x = packh2(v.x, v.y);
    u.y = packh2(v.z, v.w);
    *(uint2*)(g_xh + i) = u;
}

__global__ void prep_w(const float* __restrict__ Wq,
                       const float* __restrict__ Wk,
                       const float* __restrict__ Wv) {
    __shared__ float t[32][33];
    const int z = blockIdx.z;
    const float* W = (z == 0) ? Wq : (z == 1) ? Wk : Wv;
    const int n0 = blockIdx.x * 32, k0 = blockIdx.y * 32;
    const int tx = threadIdx.x, ty = threadIdx.y;
    #pragma unroll
    for (int j = 0; j < 4; j++) {
        int k = k0 + ty + j * 8;
        t[ty + j * 8][tx] = W[(size_t)k * DM + n0 + tx];
    }
    __syncthreads();
    #pragma unroll
    for (int j = 0; j < 4; j++) {
        int n = n0 + ty + j * 8;
        g_wh[(size_t)z * DM * DM + (size_t)n * DM + k0 + tx] =
            __float2half(t[tx][ty + j * 8]);
    }
}

// ---------------------------------------------------------------------------
// Kernel 1: QKV GEMM via fp16 mma.sync m16n8k16.
// Block tile 128x128, k-step 64, 2-stage cp.async double buffer.
// 8 warps 4(m)x2(n), warp tile 32x64.
// ---------------------------------------------------------------------------
#define GSH   72                 // smem row stride in halves (36 words; 4g+t banks)
#define GSW   (GSH / 2)          // in 32-bit words
#define GTILE (128 * GSH)        // halves per tile
#define SMEM_GEMM (2 * 2 * GTILE * 2)   // bytes: 2 stages x (A+B)

__global__ __launch_bounds__(256, 2)
void qkv_fp16(const float* __restrict__ bq, const float* __restrict__ bk,
              const float* __restrict__ bv)
{
    extern __shared__ __half sh[];
    const int tid  = threadIdx.x;
    const int lane = tid & 31;
    const int warp = tid >> 5;
    const int g    = lane >> 2;
    const int t    = lane & 3;
    const int mw   = warp >> 1;
    const int nw   = warp & 1;
    const int z    = blockIdx.z;
    const int m0   = blockIdx.y * 128;
    const int n0   = blockIdx.x * 128;

    const __half* Ag = g_xh + (size_t)m0 * DM;
    const __half* Bg = g_wh + (size_t)z * DM * DM + (size_t)n0 * DM;
    const uint32_t su = smem_u32(sh);

    float c[2][8][4];
    #pragma unroll
    for (int mt = 0; mt < 2; mt++)
        #pragma unroll
        for (int nt = 0; nt < 8; nt++)
            #pragma unroll
            for (int r = 0; r < 4; r++) c[mt][nt][r] = 0.0f;

    auto fill = [&](int s, int kt) {
        uint32_t base = su + (uint32_t)s * (2 * GTILE * 2);
        #pragma unroll
        for (int i = 0; i < 4; i++) {
            int idx = tid + i * 256;           // 1024 slots: 128 rows x 8 chunks
            int row = idx >> 3;
            int j   = idx & 7;
            uint32_t off = (uint32_t)(row * GSH + j * 8) * 2;
            cp16(base + off,                 Ag + (size_t)row * DM + kt * 64 + j * 8);
            cp16(base + GTILE * 2 + off,     Bg + (size_t)row * DM + kt * 64 + j * 8);
        }
        asm volatile("cp.async.commit_group;" ::: "memory");
    };

    fill(0, 0);
    for (int kt = 0; kt < 16; kt++) {
        const int s = kt & 1;
        if (kt + 1 < 16) {
            fill(s ^ 1, kt + 1);              // stage s^1 fully consumed at kt-1
            asm volatile("cp.async.wait_group 1;" ::: "memory");
        } else {
            asm volatile("cp.async.wait_group 0;" ::: "memory");
        }
        __syncthreads();

        const uint32_t* pA = (const uint32_t*)(sh + s * 2 * GTILE);
        const uint32_t* pB = pA + GTILE / 2;

        #pragma unroll
        for (int kc = 0; kc < 4; kc++) {
            uint32_t a[2][4];
            #pragma unroll
            for (int mt = 0; mt < 2; mt++) {
                int wb = (mw * 32 + mt * 16 + g) * GSW + kc * 8 + t;
                a[mt][0] = pA[wb];
                a[mt][1] = pA[wb + 8 * GSW];
                a[mt][2] = pA[wb + 4];
                a[mt][3] = pA[wb + 8 * GSW + 4];
            }
            uint32_t b[8][2];
            #pragma unroll
            for (int nt = 0; nt < 8; nt++) {
                int wb = (nw * 64 + nt * 8 + g) * GSW + kc * 8 + t;
                b[nt][0] = pB[wb];
                b[nt][1] = pB[wb + 4];
            }
            #pragma unroll
            for (int mt = 0; mt < 2; mt++)
                #pragma unroll
                for (int nt = 0; nt < 8; nt++)
                    mma16(c[mt][nt], a[mt], b[nt][0], b[nt][1]);
        }
        __syncthreads();
    }

    // Epilogue: bias add (+1/8 scale for Q), store fp16 to [B,H,N,HD].
    const float* bias = (z == 0) ? bq : (z == 1) ? bk : bv;
    __half* Out = (z == 0) ? g_qh : (z == 1) ? g_kh : g_vh;
    const float qs = (z == 0) ? 0.125f : 1.0f;

    #pragma unroll
    for (int mt = 0; mt < 2; mt++) {
        int row  = mw * 32 + mt * 16 + g;
        int m    = m0 + row;
        int b    = m >> 11;
        int n    = m & (SEQ - 1);
        #pragma unroll
        for (int nt = 0; nt < 8; nt++) {
            int gcol = n0 + nw * 64 + nt * 8 + 2 * t;
            int h    = gcol >> 6;
            int hd   = gcol & 63;
            float bx = bias[gcol], by = bias[gcol + 1];
            __half* dst = Out + ((size_t)((b * NH + h) * SEQ + n)) * HDIM + hd;
            *(uint32_t*)dst =
                packh2((c[mt][nt][0] + bx) * qs, (c[mt][nt][1] + by) * qs);
            *(uint32_t*)(dst + 8 * HDIM) =
                packh2((c[mt][nt][2] + bx) * qs, (c[mt][nt][3] + by) * qs);
        }
    }
}

// ---------------------------------------------------------------------------
// Kernel 2: causal flash attention, fp16 mma, register-resident P.
// Block: one (b,h), 128-query tile; 8 warps, warp owns 16 rows.
// K tile 64. Q frags from global; K frags manual LDS; V frags ldmatrix.trans.
// ---------------------------------------------------------------------------
__global__ __launch_bounds__(256, 2)
void flash_fp16(float* __restrict__ out)
{
    __shared__ __half sK[64 * GSH];
    __shared__ __half sV[64 * GSH];

    const int tid  = threadIdx.x;
    const int lane = tid & 31;
    const int warp = tid >> 5;
    const int g    = lane >> 2;
    const int t    = lane & 3;
    const int qt   = blockIdx.x;
    const int bh   = blockIdx.y;
    const int q0   = qt * 128;

    const __half* Qg = g_qh + (size_t)bh * SEQ * HDIM;
    const __half* Kg = g_kh + (size_t)bh * SEQ * HDIM;
    const __half* Vg = g_vh + (size_t)bh * SEQ * HDIM;

    // Q fragments straight from global (warp-private rows; Q pre-scaled).
    uint32_t qa[4][4];
    const int qrow = q0 + warp * 16 + g;
    #pragma unroll
    for (int kc = 0; kc < 4; kc++) {
        const uint32_t* q1 = (const uint32_t*)(Qg + (size_t)qrow * HDIM + kc * 16 + 2 * t);
        const uint32_t* q2 = (const uint32_t*)(Qg + (size_t)(qrow + 8) * HDIM + kc * 16 + 2 * t);
        qa[kc][0] = q1[0];
        qa[kc][1] = q2[0];
        qa[kc][2] = q1[4];
        qa[kc][3] = q2[4];
    }

    float o[8][4];
    #pragma unroll
    for (int nt = 0; nt < 8; nt++)
        #pragma unroll
        for (int r = 0; r < 4; r++) o[nt][r] = 0.0f;
    float m0r = -INFINITY, m1r = -INFINITY, l0 = 0.0f, l1 = 0.0f;

    const uint32_t svu = smem_u32(sV);
    const int krow = (lane & 7) + ((lane >> 3) & 1) * 8;   // ldmatrix row select
    const int dsel = (lane >> 4) * 8;                      // ldmatrix col select

    const int nkt = 2 * qt + 2;
    for (int jt = 0; jt < nkt; jt++) {
        const int k0 = jt * 64;
        __syncthreads();   // prior PV reads of sV / S reads of sK complete

        // Load K,V tiles (already fp16): straight uint4 copies.
        #pragma unroll
        for (int it = 0; it < 2; it++) {
            int idx = tid + it * 256;          // 512 slots: 64 rows x 8 chunks
            int row = idx >> 3;
            int j   = idx & 7;
            *(uint4*)&sK[row * GSH + j * 8] =
                *(const uint4*)&Kg[(size_t)(k0 + row) * HDIM + j * 8];
            *(uint4*)&sV[row * GSH + j * 8] =
                *(const uint4*)&Vg[(size_t)(k0 + row) * HDIM + j * 8];
        }
        __syncthreads();

        // S = Q K^T (warp rows 16 x 64 keys).
        float s[8][4];
        #pragma unroll
        for (int nt = 0; nt < 8; nt++)
            #pragma unroll
            for (int r = 0; r < 4; r++) s[nt][r] = 0.0f;

        const uint32_t* pk = (const uint32_t*)sK;
        #pragma unroll
        for (int kc = 0; kc < 4; kc++) {
            #pragma unroll
            for (int nt = 0; nt < 8; nt++) {
                int wb = (nt * 8 + g) * GSW + kc * 8 + t;
                mma16(s[nt], qa[kc], pk[wb], pk[wb + 4]);
            }
        }

        // Causal mask (last two key tiles only).
        if (jt >= 2 * qt) {
            int r0 = qrow;
            int r1 = r0 + 8;
            #pragma unroll
            for (int nt = 0; nt < 8; nt++) {
                int key = k0 + nt * 8 + 2 * t;
                if (key     > r0) s[nt][0] = -1e30f;
                if (key + 1 > r0) s[nt][1] = -1e30f;
                if (key     > r1) s[nt][2] = -1e30f;
                if (key + 1 > r1) s[nt][3] = -1e30f;
            }
        }

        // Online softmax (rows r0: regs 0,1; rows r0+8: regs 2,3).
        float mx0 = -INFINITY, mx1 = -INFINITY;
        #pragma unroll
        for (int nt = 0; nt < 8; nt++) {
            mx0 = fmaxf(mx0, fmaxf(s[nt][0], s[nt][1]));
            mx1 = fmaxf(mx1, fmaxf(s[nt][2], s[nt][3]));
        }
        mx0 = fmaxf(mx0, __shfl_xor_sync(0xffffffffu, mx0, 1));
        mx0 = fmaxf(mx0, __shfl_xor_sync(0xffffffffu, mx0, 2));
        mx1 = fmaxf(mx1, __shfl_xor_sync(0xffffffffu, mx1, 1));
        mx1 = fmaxf(mx1, __shfl_xor_sync(0xffffffffu, mx1, 2));

        float mn0 = fmaxf(m0r, mx0), mn1 = fmaxf(m1r, mx1);
        float a0 = __expf(m0r - mn0), a1 = __expf(m1r - mn1);
        float ps0 = 0.0f, ps1 = 0.0f;
        #pragma unroll
        for (int nt = 0; nt < 8; nt++) {
            s[nt][0] = __expf(s[nt][0] - mn0); ps0 += s[nt][0];
            s[nt][1] = __expf(s[nt][1] - mn0); ps0 += s[nt][1];
            s[nt][2] = __expf(s[nt][2] - mn1); ps1 += s[nt][2];
            s[nt][3] = __expf(s[nt][3] - mn1); ps1 += s[nt][3];
        }
        ps0 += __shfl_xor_sync(0xffffffffu, ps0, 1);
        ps0 += __shfl_xor_sync(0xffffffffu, ps0, 2);
        ps1 += __shfl_xor_sync(0xffffffffu, ps1, 1);
        ps1 += __shfl_xor_sync(0xffffffffu, ps1, 2);
        l0 = l0 * a0 + ps0; l1 = l1 * a1 + ps1;
        m0r = mn0; m1r = mn1;

        #pragma unroll
        for (int nt = 0; nt < 8; nt++) {
            o[nt][0] *= a0; o[nt][1] *= a0;
            o[nt][2] *= a1; o[nt][3] *= a1;
        }

        // P: S accumulators -> fp16 A-fragments (no smem round-trip).
        uint32_t pa[4][4];
        #pragma unroll
        for (int kc = 0; kc < 4; kc++) {
            pa[kc][0] = packh2(s[2 * kc][0],     s[2 * kc][1]);
            pa[kc][1] = packh2(s[2 * kc][2],     s[2 * kc][3]);
            pa[kc][2] = packh2(s[2 * kc + 1][0], s[2 * kc + 1][1]);
            pa[kc][3] = packh2(s[2 * kc + 1][2], s[2 * kc + 1][3]);
        }

        // O += P V : V fragments via ldmatrix.x4.trans.
        #pragma unroll
        for (int kc = 0; kc < 4; kc++) {
            #pragma unroll
            for (int nt2 = 0; nt2 < 4; nt2++) {
                uint32_t addr = svu +
                    (uint32_t)(((kc * 16 + krow) * GSH) + nt2 * 16 + dsel) * 2;
                uint32_t r[4];
                ldsm4t(r, addr);
                mma16(o[2 * nt2],     pa[kc], r[0], r[1]);
                mma16(o[2 * nt2 + 1], pa[kc], r[2], r[3]);
            }
        }
    }

    // Epilogue: normalize, write fp32 [B,N,D].
    const int b  = bh >> 4;
    const int h  = bh & 15;
    const float i0 = 1.0f / l0, i1 = 1.0f / l1;
    #pragma unroll
    for (int nt = 0; nt < 8; nt++) {
        int col = h * HDIM + nt * 8 + 2 * t;
        float2 v0 = { o[nt][0] * i0, o[nt][1] * i0 };
        *(float2*)(out + ((size_t)(b * SEQ + qrow)) * DM + col) = v0;
        float2 v1 = { o[nt][2] * i1, o[nt][3] * i1 };
        *(float2*)(out + ((size_t)(b * SEQ + qrow + 8)) * DM + col) = v1;
    }
}

// ---------------------------------------------------------------------------
// Launch
// ---------------------------------------------------------------------------
extern "C" void kernel_launch(void* const* d_in, const int* in_sizes, int n_in,
                              void* d_out, int out_size)
{
    const float* x = (const float*)d_in[0];

    int base = 1;
    if (n_in >= 8 && in_sizes[1] == SEQ * SEQ) base = 2;

    const float* Wq = (const float*)d_in[base + 0];
    const float* bq = (const float*)d_in[base + 1];
    const float* Wk = (const float*)d_in[base + 2];
    const float* bk = (const float*)d_in[base + 3];
    const float* Wv = (const float*)d_in[base + 4];
    const float* bv = (const float*)d_in[base + 5];
    float* out = (float*)d_out;

    prep_x<<<(BB * SEQ * DM / 4) / 256, 256>>>(x);
    prep_w<<<dim3(DM / 32, DM / 32, 3), dim3(32, 8)>>>(Wq, Wk, Wv);

    cudaFuncSetAttribute(qkv_fp16, cudaFuncAttributeMaxDynamicSharedMemorySize,
                         SMEM_GEMM);
    qkv_fp16<<<dim3(DM / 128, (BB * SEQ) / 128, 3), 256, SMEM_GEMM>>>(bq, bk, bv);

    flash_fp16<<<dim3(SEQ / 128, BH), 256>>>(out);
}